// round 9
// baseline (speedup 1.0000x reference)
#include <cuda_runtime.h>
#include <cstdint>

#define NN 128
#define NEGF   (-9999.0f)
#define THRESHF (-9000.0f)

// ---------------------------------------------------------------------------
// Order-preserving float <-> uint mapping (monotone under unsigned compare)
// ---------------------------------------------------------------------------
__device__ __forceinline__ unsigned f2o(float f) {
    unsigned u = __float_as_uint(f);
    return (u & 0x80000000u) ? ~u : (u | 0x80000000u);
}
__device__ __forceinline__ float o2f(unsigned k) {
    return __uint_as_float((k & 0x80000000u) ? (k & 0x7fffffffu) : ~k);
}

// Warp-wide argmax with FIRST-occurrence tie break (matches jnp.argmax).
// Each lane holds (val, idx); idx is the smallest index at which this lane saw
// its val. Result broadcast to all lanes.
__device__ __forceinline__ void warp_argmax(float& val, int& idx) {
    unsigned key = f2o(val);
    unsigned mx  = __reduce_max_sync(0xffffffffu, key);
    int cand = (key == mx) ? idx : 0x7fffffff;
    idx = __reduce_min_sync(0xffffffffu, cand);
    val = o2f(mx);
}

// ---------------------------------------------------------------------------
// Output init: scores = NEG (0 on diagonal), backtrace = 0. Layout:
//   [0,                B*N*N*4) : scores  [b][i][j][d][c]  (d*2+c)
//   [B*N*N*4,        2*B*N*N*4) : backtrace (as float)
// ---------------------------------------------------------------------------
__global__ void init_out_kernel(float* __restrict__ out, int B) {
    const int N = NN;
    int total = B * N * N * 4;           // scores region
    int grand = 2 * total;
    for (int t = blockIdx.x * blockDim.x + threadIdx.x; t < grand;
         t += gridDim.x * blockDim.x) {
        if (t < total) {
            int cell = t >> 2;           // b*N*N + i*N + j
            int ij = cell & (N * N - 1);
            int i = ij >> 7;
            int j = ij & (N - 1);
            out[t] = (i == j) ? 0.0f : NEGF;
        } else {
            out[t] = 0.0f;
        }
    }
}

// ---------------------------------------------------------------------------
// Eisner DP. One CTA per batch item. Chart packing in shared memory
// (diagonals of all charts are identically 0, so upper/lower can share):
//   A [r][c]: r<c -> S11[r][c]            ; r>c -> S01[c][r]
//   Bm[r][c]: r<c -> S01[r][c]            ; r>c -> S00[c][r]
//   Cm[r][c]: r<c -> S10[r][c]            ; r>c -> S11[c][r]
// All inner-loop reads become ROW accesses (conflict-free, stride-1 in q):
//   base = A [i][q] + A [j][q+1]   (S11[i][q]   + S01[q+1][j])
//   c01  = Bm[i][q] + Bm[j][q]     (S01[i][q]   + S00[q][j])
//   c11  = Cm[i][q] + Cm[j][q]     (S10[i][q]   + S11[q][j])
// ---------------------------------------------------------------------------
extern __shared__ float g_smem[];

__global__ __launch_bounds__(1024, 1)
void eisner_dp_kernel(const float* __restrict__ vinfo_all,
                      float* __restrict__ out, int B) {
    const int N = NN;
    float* A  = g_smem;
    float* Bm = g_smem + N * N;
    float* Cm = g_smem + 2 * N * N;

    const int b = blockIdx.x;
    const float* __restrict__ vinfo = vinfo_all + (size_t)b * N * N;
    float* __restrict__ outS = out + (size_t)b * N * N * 4;
    float* __restrict__ outB = out + (size_t)B * N * N * 4 + (size_t)b * N * N * 4;

    const int tid  = threadIdx.x;
    const int lane = tid & 31;
    const int warp = tid >> 5;

    // Init packed charts: NEG off-diagonal, 0 on diagonal.
    for (int t = tid; t < N * N; t += blockDim.x) {
        float v = ((t >> 7) == (t & (N - 1))) ? 0.0f : NEGF;
        A[t] = v; Bm[t] = v; Cm[t] = v;
    }
    __syncthreads();

    for (int k = 1; k < N; ++k) {
        // one warp per span (i, j=i+k)
        for (int i = warp; i + k < N; i += 32) {
            const int j = i + k;
            const float vL = __ldg(&vinfo[j * N + i]);   // vinfo[j][i]
            const float vR = __ldg(&vinfo[i * N + j]);   // vinfo[i][j]

            float b00v = NEGF, b10v = NEGF, b01v = NEGF, b11v = NEGF;
            int   b00i = 0,    b10i = 0,    b01i = 0,    b11i = 0;
            float p00m0 = NEGF;   // lane 0 keeps the m==0 candidate of p00

            const float* Ai  = A  + i * N;
            const float* Aj  = A  + j * N;
            const float* Bmi = Bm + i * N;
            const float* Bmj = Bm + j * N;
            const float* Cmi = Cm + i * N;
            const float* Cmj = Cm + j * N;

            for (int m = lane; m < k; m += 32) {
                const int q = i + m;
                // exact reference arithmetic order: ((S11+S01) + v) + 5.0
                float base = Ai[q] + Aj[q + 1];
                float t00  = fmaxf((base + vL) + 5.0f, NEGF);
                float t10  = fmaxf((base + vR) + 5.0f, NEGF);
                if (t00 > b00v) { b00v = t00; b00i = m; }
                if (t10 > b10v) { b10v = t10; b10i = m; }
                if (m == 0) p00m0 = t00;
                if (m >= 1) {
                    float c01 = fmaxf(Bmi[q] + Bmj[q], NEGF);
                    float c11 = fmaxf(Cmi[q] + Cmj[q], NEGF);
                    if (c01 > b01v) { b01v = c01; b01i = m; }
                    if (c11 > b11v) { b11v = c11; b11i = m; }
                }
            }

            warp_argmax(b00v, b00i);
            warp_argmax(b10v, b10i);
            warp_argmax(b01v, b01i);
            warp_argmax(b11v, b11i);

            // c01[m=0] = part00 (the (0,0) cell as updated by q=i only)
            float part00 = __shfl_sync(0xffffffffu, p00m0, 0);
            if (!(part00 > THRESHF)) part00 = NEGF;
            if (part00 >= b01v) { b01v = part00; b01i = 0; }  // idx 0 wins ties

            // c11[m=k] = new10 (fully updated (1,0) cell); largest index ->
            // earlier split wins ties -> strict >
            float new10 = (b10v > THRESHF) ? b10v : NEGF;
            if (new10 > b11v) { b11v = new10; b11i = k; }

            if (lane == 0) {
                const bool ok00 = b00v > THRESHF;
                const bool ok10 = b10v > THRESHF;
                const bool ok01 = b01v > THRESHF;
                const bool ok11 = b11v > THRESHF;
                const int base4 = (i * N + j) * 4;   // [i][j][d][c], off = d*2+c
                if (ok00) {                           // S00[i][j]
                    Bm[j * N + i] = b00v;
                    outS[base4 + 0] = b00v;
                    outB[base4 + 0] = (float)(i + b00i);
                }
                if (ok10) {                           // S10[i][j]
                    Cm[i * N + j] = b10v;
                    outS[base4 + 2] = b10v;
                    outB[base4 + 2] = (float)(i + b10i);
                }
                if (ok01) {                           // S01[i][j]
                    A[j * N + i]  = b01v;
                    Bm[i * N + j] = b01v;
                    outS[base4 + 1] = b01v;
                    outB[base4 + 1] = (float)(i + b01i);
                }
                if (ok11) {                           // S11[i][j]
                    A[i * N + j]  = b11v;
                    Cm[j * N + i] = b11v;
                    outS[base4 + 3] = b11v;
                    outB[base4 + 3] = (float)(i + b11i);
                }
            }
        }
        __syncthreads();   // width-k cells finalized before width-(k+1) reads
    }
}

// ---------------------------------------------------------------------------
extern "C" void kernel_launch(void* const* d_in, const int* in_sizes, int n_in,
                              void* d_out, int out_size) {
    const float* vinfo = (const float*)d_in[0];
    int B = (n_in > 1 && in_sizes[1] > 0) ? in_sizes[1]
                                          : in_sizes[0] / (NN * NN);
    float* out = (float*)d_out;
    (void)out_size;

    // Fill defaults (NEG/diag-0 scores, zero backtrace); DP overwrites cells
    // that pass the threshold.
    init_out_kernel<<<1024, 256>>>(out, B);

    const int smem_bytes = 3 * NN * NN * (int)sizeof(float);   // 192 KB
    cudaFuncSetAttribute(eisner_dp_kernel,
                         cudaFuncAttributeMaxDynamicSharedMemorySize,
                         smem_bytes);
    eisner_dp_kernel<<<B, 1024, smem_bytes>>>(vinfo, out, B);
}